// round 11
// baseline (speedup 1.0000x reference)
#include <cuda_runtime.h>
#include <cstdint>

#define NPG 524288           // elements per (b, group)
#define NTOT 33554432        // B*C*H*W

// ---------------- device scratch (static allocation only) ----------------
static __device__ float  d_part[1024 * 2];    // per-block GN partials (sum, sumsq)
static __device__ float  d_weff[8 * 8192];    // [b][k][o], o = c*2 + {0=gate,1=upd}
static __device__ float  d_biaseff[8 * 128];  // [b][o] interleaved
static __device__ float  d_gate[NTOT];        // sigmoid(gate logits)
static __device__ float  d_hw[NTOT];          // column-scan result

// ---------------- f32x2 packed FMA helpers --------------------------------
__device__ __forceinline__ unsigned long long fma2(unsigned long long a,
                                                   unsigned long long b,
                                                   unsigned long long c) {
    unsigned long long d;
    asm("fma.rn.f32x2 %0, %1, %2, %3;" : "=l"(d) : "l"(a), "l"(b), "l"(c));
    return d;
}
__device__ __forceinline__ unsigned long long pack2(float lo, float hi) {
    unsigned long long d;
    asm("mov.b64 %0, {%1, %2};" : "=l"(d) : "f"(lo), "f"(hi));
    return d;
}
__device__ __forceinline__ void unpack2(unsigned long long v, float& lo, float& hi) {
    asm("mov.b64 {%0, %1}, %2;" : "=f"(lo), "=f"(hi) : "l"(v));
}
__device__ __forceinline__ float sigmoid_tanh(float z) {
    float t;
    asm("tanh.approx.f32 %0, %1;" : "=f"(t) : "f"(z * 0.5f));
    return fmaf(0.5f, t, 0.5f);
}

// ---------------- K1: GN partial stats (atomic-free) ---------------------
__global__ __launch_bounds__(256) void k_gn_stats(const float* __restrict__ x) {
    const int grp   = blockIdx.x >> 4;
    const int slice = blockIdx.x & 15;
    const float4* p = (const float4*)x + (size_t)grp * 131072 + slice * 8192;
    float s = 0.f, ss = 0.f;
#pragma unroll 4
    for (int i = threadIdx.x; i < 8192; i += 256) {
        float4 v = p[i];
        s  += (v.x + v.y) + (v.z + v.w);
        ss += (v.x * v.x + v.y * v.y) + (v.z * v.z + v.w * v.w);
    }
    for (int off = 16; off; off >>= 1) {
        s  += __shfl_down_sync(0xffffffffu, s,  off);
        ss += __shfl_down_sync(0xffffffffu, ss, off);
    }
    __shared__ float rs[8], rss[8];
    int w = threadIdx.x >> 5, l = threadIdx.x & 31;
    if (l == 0) { rs[w] = s; rss[w] = ss; }
    __syncthreads();
    if (threadIdx.x == 0) {
        float S = 0.f, SS = 0.f;
#pragma unroll
        for (int i = 0; i < 8; i++) { S += rs[i]; SS += rss[i]; }
        d_part[blockIdx.x * 2 + 0] = S;
        d_part[blockIdx.x * 2 + 1] = SS;
    }
}

// ---------------- K2: finalize stats + fold GN affine into weights -------
__global__ __launch_bounds__(256) void k_weff(const float* __restrict__ gw,
                                              const float* __restrict__ gb,
                                              const float* __restrict__ uw,
                                              const float* __restrict__ ub,
                                              const float* __restrict__ gnw,
                                              const float* __restrict__ gnb) {
    const int b = blockIdx.x >> 3;
    const int slice = blockIdx.x & 7;
    __shared__ float smu[8], srstd[8];
    if (threadIdx.x < 8) {
        int g = b * 8 + threadIdx.x;
        double S = 0.0, SS = 0.0;
#pragma unroll
        for (int i = 0; i < 16; i++) {
            S  += (double)d_part[(g * 16 + i) * 2 + 0];
            SS += (double)d_part[(g * 16 + i) * 2 + 1];
        }
        const double n = (double)NPG;
        double mu  = S / n;
        double var = SS / n - mu * mu;
        smu[threadIdx.x]   = (float)mu;
        srstd[threadIdx.x] = (float)(1.0 / sqrt(var + 1e-5));
    }
    __syncthreads();
    const int base = slice * 1024;
#pragma unroll 4
    for (int i = 0; i < 4; i++) {
        int idx = base + i * 256 + threadIdx.x;
        int k = idx >> 7, o = idx & 127;
        float w = (o < 64) ? gw[o * 64 + k] : uw[(o - 64) * 64 + k];
        d_weff[b * 8192 + k * 128 + (o & 63) * 2 + (o >> 6)] =
            w * gnw[k] * srstd[k >> 3];
    }
    if (slice == 0 && threadIdx.x < 128) {
        int m = threadIdx.x;           // interleaved output index
        int cc = m >> 1, gu = m & 1;
        float acc = gu ? ub[cc] : gb[cc];
#pragma unroll 8
        for (int k = 0; k < 64; k++) {
            float w = gu ? uw[cc * 64 + k] : gw[cc * 64 + k];
            int g = k >> 3;
            acc += w * (gnb[k] - smu[g] * srstd[g] * gnw[k]);
        }
        d_biaseff[b * 128 + m] = acc;
    }
}

// ---------------- K3: 8x8 register-tiled GEMM + column scan --------------
// Grid 2048 = 8 b x 256 h, 128 threads, 2 CTAs/SM (102KB dynamic smem).
// GEMM thread tile: 8 outputs (og = t>>3) x 8 px (pg = t&7); chunk = 64 px,
// 4 iters/row. Per k per warp: 2 LDS.128 (w) + 2 LDS.128 (px) = 16 crossbar
// cyc vs 16 fma cyc -> balanced (R7 was 2.25x crossbar-over).
// Scan: thread = (c = t>>1, q = t&1) owns 32 px; R7 exchange pattern.
// 128-thread CTA -> 256-reg budget: no spills by construction.
__global__ __launch_bounds__(128) void k_colgemm(const float* __restrict__ x) {
    extern __shared__ float sm[];
    float* wsm = sm;                  // [k][o]       64*128      = 8192 f
    float* xsm = sm + 8192;           // [buf][k][68] 2*64*68     = 8704 f
    float* lsm = sm + 16896;          // [o][72]      128*72      = 9216 f

    const int t  = threadIdx.x;
    const int b  = blockIdx.x >> 8;
    const int h  = blockIdx.x & 255;
    const int og = t >> 3;            // 0..15: outputs og*8..+7
    const int pg = t & 7;             // 0..7 : px pg*8..+7 within chunk
    const int c  = t >> 1;            // scan channel
    const int q  = t & 1;             // scan half (32 px)
    const unsigned FULL = 0xffffffffu;

    // weights -> smem (pre-interleaved layout; straight float4 copy)
    {
        const float4* wsrc = (const float4*)(d_weff + b * 8192);
        float4* wdst = (float4*)wsm;
#pragma unroll
        for (int i = 0; i < 16; i++) wdst[t + i * 128] = wsrc[t + i * 128];
    }
    float biasr[8];
#pragma unroll
    for (int j = 0; j < 8; j++) biasr[j] = d_biaseff[b * 128 + og * 8 + j];

    // X loaders: 8 float4/thread/chunk. sl = t + i*128 -> ch = sl>>4, f = sl&15
    const float* xb = x + (size_t)b * 64 * 65536 + (size_t)h * 256;
    const float* gp[8];
    int so[8];
#pragma unroll
    for (int i = 0; i < 8; i++) {
        int sl = t + i * 128;
        gp[i] = xb + (size_t)(sl >> 4) * 65536 + (sl & 15) * 4;
        so[i] = (sl >> 4) * 68 + (sl & 15) * 4;
    }
    float4 vin[8];
    // chunk 0 -> xsm[0]
#pragma unroll
    for (int i = 0; i < 8; i++) vin[i] = *(const float4*)gp[i];
#pragma unroll
    for (int i = 0; i < 8; i++) *(float4*)&xsm[so[i]] = vin[i];
    // prefetch chunk 1
#pragma unroll
    for (int i = 0; i < 8; i++) vin[i] = *(const float4*)(gp[i] + 64);
    __syncthreads();                  // xsm[0] + wsm visible

    float s_prev = 0.f;
    const size_t obase = ((size_t)(b * 64 + c)) * 65536 + (size_t)h * 256;

#pragma unroll 1
    for (int it = 0; it < 4; it++) {
        const int buf = it & 1;
        // ---- GEMM: 8 out x 8 px, K=64 ----
        unsigned long long acc[8][4];
#pragma unroll
        for (int j = 0; j < 8; j++) {
            unsigned long long bb = pack2(biasr[j], biasr[j]);
            acc[j][0] = bb; acc[j][1] = bb; acc[j][2] = bb; acc[j][3] = bb;
        }
        {
            const float* xs = xsm + buf * 4352 + pg * 8;
            const float* ws = wsm + og * 8;
#pragma unroll 8
            for (int k = 0; k < 64; k++) {
                float4 w0 = *(const float4*)(ws + k * 128);
                float4 w1 = *(const float4*)(ws + k * 128 + 4);
                ulonglong2 p0 = *(const ulonglong2*)(xs + k * 68);
                ulonglong2 p1 = *(const ulonglong2*)(xs + k * 68 + 4);
                float w[8] = {w0.x, w0.y, w0.z, w0.w, w1.x, w1.y, w1.z, w1.w};
#pragma unroll
                for (int j = 0; j < 8; j++) {
                    unsigned long long w2 = pack2(w[j], w[j]);
                    acc[j][0] = fma2(w2, p0.x, acc[j][0]);
                    acc[j][1] = fma2(w2, p0.y, acc[j][1]);
                    acc[j][2] = fma2(w2, p1.x, acc[j][2]);
                    acc[j][3] = fma2(w2, p1.y, acc[j][3]);
                }
            }
        }
        // stage chunk it+1 into other buffer (its readers done since it-1)
        if (it < 3) {
#pragma unroll
            for (int i = 0; i < 8; i++)
                *(float4*)&xsm[(buf ^ 1) * 4352 + so[i]] = vin[i];
        }
        // prefetch chunk it+2
        if (it < 2) {
#pragma unroll
            for (int i = 0; i < 8; i++)
                vin[i] = *(const float4*)(gp[i] + (it + 2) * 64);
        }
        // ---- logits -> lsm (stride 72: 2-way max conflicts) ----
#pragma unroll
        for (int j = 0; j < 8; j++) {
            float4 v0, v1;
            unpack2(acc[j][0], v0.x, v0.y);
            unpack2(acc[j][1], v0.z, v0.w);
            unpack2(acc[j][2], v1.x, v1.y);
            unpack2(acc[j][3], v1.z, v1.w);
            float* lp = &lsm[(og * 8 + j) * 72 + pg * 8];
            *(float4*)lp       = v0;
            *(float4*)(lp + 4) = v1;
        }
        __syncthreads();              // lsm visible; xsm[buf] free

        // ---- scan: thread (c, q) owns px q*32..+31 of this 64-px chunk ----
        float gv[32], uv[32];
        {
            const float4* lg = (const float4*)&lsm[(2 * c) * 72 + q * 32];
            const float4* lu = (const float4*)&lsm[(2 * c + 1) * 72 + q * 32];
#pragma unroll
            for (int j4 = 0; j4 < 8; j4++) {
                float4 a = lg[j4], d = lu[j4];
                gv[j4*4+0] = a.x; gv[j4*4+1] = a.y;
                gv[j4*4+2] = a.z; gv[j4*4+3] = a.w;
                uv[j4*4+0] = d.x; uv[j4*4+1] = d.y;
                uv[j4*4+2] = d.z; uv[j4*4+3] = d.w;
            }
        }
#pragma unroll
        for (int j = 0; j < 32; j++) {
            gv[j] = sigmoid_tanh(gv[j]);
            uv[j] = fmaf(-gv[j], uv[j], uv[j]);   // (1-g)*u
        }
        // composite over own 32 px
        float Ac = 1.f, Bc = 0.f;
#pragma unroll
        for (int j = 0; j < 32; j++) {
            Ac = Ac * gv[j];
            Bc = fmaf(gv[j], Bc, uv[j]);
        }
        // exchange with neighbour half (lane^1)
        float Ao = __shfl_xor_sync(FULL, Ac, 1);
        float Bo = __shfl_xor_sync(FULL, Bc, 1);
        float Af = (q == 0) ? Ac : Ao;    // first-half composite
        float Bf = (q == 0) ? Bc : Bo;
        float As = (q == 0) ? Ao : Ac;    // second-half composite
        float Bs = (q == 0) ? Bo : Bc;
        float sin0 = (q == 0) ? s_prev : fmaf(Af, s_prev, Bf);
        s_prev = fmaf(As, fmaf(Af, s_prev, Bf), Bs);

        // sequential re-apply + writeback (8+8 STG.128)
        float* gout = d_gate + obase + it * 64 + q * 32;
        float* hout = d_hw   + obase + it * 64 + q * 32;
        float s = sin0;
#pragma unroll
        for (int j4 = 0; j4 < 8; j4++) {
            float4 sv;
            s = fmaf(gv[j4*4+0], s, uv[j4*4+0]); sv.x = s;
            s = fmaf(gv[j4*4+1], s, uv[j4*4+1]); sv.y = s;
            s = fmaf(gv[j4*4+2], s, uv[j4*4+2]); sv.z = s;
            s = fmaf(gv[j4*4+3], s, uv[j4*4+3]); sv.w = s;
            *(float4*)(gout + j4 * 4) =
                make_float4(gv[j4*4], gv[j4*4+1], gv[j4*4+2], gv[j4*4+3]);
            *(float4*)(hout + j4 * 4) = sv;
        }
        __syncthreads();              // lsm free for next iter; staging visible
    }
}

// ---------------- K4: row scan over H + residual add ---------------------
__global__ __launch_bounds__(128) void k_rowscan(const float* __restrict__ x,
                                                 float* __restrict__ out) {
    const int idx  = blockIdx.x * 128 + threadIdx.x;     // 0..131071
    const int base = (idx >> 8) * 65536 + (idx & 255);   // (b*64+c)*HW + w
    float s = 0.f;
#pragma unroll 1
    for (int h = 0; h < 256; h += 8) {
        const int r = base + (h << 8);
        float g[8], u[8], xv[8];
#pragma unroll
        for (int j = 0; j < 8; j++) g[j] = d_gate[r + (j << 8)];
#pragma unroll
        for (int j = 0; j < 8; j++) u[j] = d_hw[r + (j << 8)];
#pragma unroll
        for (int j = 0; j < 8; j++) xv[j] = __ldcs(&x[r + (j << 8)]);
#pragma unroll
        for (int j = 0; j < 8; j++) {
            s = fmaf(g[j], s, fmaf(-g[j], u[j], u[j]));
            __stcs(&out[r + (j << 8)], xv[j] + s);
        }
    }
}

// ---------------- launch --------------------------------------------------
#define COLGEMM_SMEM (26112 * 4)   // 104,448 bytes

extern "C" void kernel_launch(void* const* d_in, const int* in_sizes, int n_in,
                              void* d_out, int out_size) {
    const float* x      = (const float*)d_in[0];
    const float* gn_w   = (const float*)d_in[1];
    const float* gn_b   = (const float*)d_in[2];
    const float* gate_w = (const float*)d_in[3];
    const float* gate_b = (const float*)d_in[4];
    const float* upd_w  = (const float*)d_in[5];
    const float* upd_b  = (const float*)d_in[6];
    float* out = (float*)d_out;

    cudaFuncSetAttribute(k_colgemm,
                         cudaFuncAttributeMaxDynamicSharedMemorySize,
                         COLGEMM_SMEM);

    k_gn_stats<<<1024, 256>>>(x);
    k_weff<<<64, 256>>>(gate_w, gate_b, upd_w, upd_b, gn_w, gn_b);
    k_colgemm<<<2048, 128, COLGEMM_SMEM>>>(x);
    k_rowscan<<<1024, 128>>>(x, out);
}

// round 12
// speedup vs baseline: 1.2428x; 1.2428x over previous
#include <cuda_runtime.h>
#include <cstdint>

#define NPG 524288           // elements per (b, group)
#define NTOT 33554432        // B*C*H*W

// ---------------- device scratch (static allocation only) ----------------
static __device__ float  d_part[1024 * 2];    // per-block GN partials (sum, sumsq)
static __device__ float  d_weff[8 * 8192];    // [b][k][c*2 + {0=gate,1=upd}]
static __device__ float  d_biaseff[8 * 128];  // [b][o], o<64 gate, o>=64 upd
static __device__ float  d_gate[NTOT];        // sigmoid(gate logits)
static __device__ float  d_hw[NTOT];          // column-scan result
static __device__ int    d_ctr;               // persistent-CTA row counter

// ---------------- f32x2 packed FMA helpers --------------------------------
__device__ __forceinline__ unsigned long long fma2(unsigned long long a,
                                                   unsigned long long b,
                                                   unsigned long long c) {
    unsigned long long d;
    asm("fma.rn.f32x2 %0, %1, %2, %3;" : "=l"(d) : "l"(a), "l"(b), "l"(c));
    return d;
}
__device__ __forceinline__ unsigned long long pack2(float lo, float hi) {
    unsigned long long d;
    asm("mov.b64 %0, {%1, %2};" : "=l"(d) : "f"(lo), "f"(hi));
    return d;
}
__device__ __forceinline__ void unpack2(unsigned long long v, float& lo, float& hi) {
    asm("mov.b64 {%0, %1}, %2;" : "=f"(lo), "=f"(hi) : "l"(v));
}
// sigmoid(z) = 0.5*tanh(0.5z) + 0.5 via MUFU.TANH
__device__ __forceinline__ float sigmoid_tanh(float z) {
    float t;
    asm("tanh.approx.f32 %0, %1;" : "=f"(t) : "f"(z * 0.5f));
    return fmaf(0.5f, t, 0.5f);
}

// ---------------- K1: GN partial stats (atomic-free) ---------------------
__global__ __launch_bounds__(256) void k_gn_stats(const float* __restrict__ x) {
    const int grp   = blockIdx.x >> 4;
    const int slice = blockIdx.x & 15;
    const float4* p = (const float4*)x + (size_t)grp * 131072 + slice * 8192;
    float s = 0.f, ss = 0.f;
#pragma unroll 4
    for (int i = threadIdx.x; i < 8192; i += 256) {
        float4 v = p[i];
        s  += (v.x + v.y) + (v.z + v.w);
        ss += (v.x * v.x + v.y * v.y) + (v.z * v.z + v.w * v.w);
    }
    for (int off = 16; off; off >>= 1) {
        s  += __shfl_down_sync(0xffffffffu, s,  off);
        ss += __shfl_down_sync(0xffffffffu, ss, off);
    }
    __shared__ float rs[8], rss[8];
    int w = threadIdx.x >> 5, l = threadIdx.x & 31;
    if (l == 0) { rs[w] = s; rss[w] = ss; }
    __syncthreads();
    if (threadIdx.x == 0) {
        float S = 0.f, SS = 0.f;
#pragma unroll
        for (int i = 0; i < 8; i++) { S += rs[i]; SS += rss[i]; }
        d_part[blockIdx.x * 2 + 0] = S;
        d_part[blockIdx.x * 2 + 1] = SS;
    }
}

// ---------------- K2: finalize stats + fold GN affine into weights -------
__global__ __launch_bounds__(256) void k_weff(const float* __restrict__ gw,
                                              const float* __restrict__ gb,
                                              const float* __restrict__ uw,
                                              const float* __restrict__ ub,
                                              const float* __restrict__ gnw,
                                              const float* __restrict__ gnb) {
    if (blockIdx.x == 0 && threadIdx.x == 0) d_ctr = 0;   // reset row counter
    const int b = blockIdx.x >> 3;
    const int slice = blockIdx.x & 7;
    __shared__ float smu[8], srstd[8];
    if (threadIdx.x < 8) {
        int g = b * 8 + threadIdx.x;
        double S = 0.0, SS = 0.0;
#pragma unroll
        for (int i = 0; i < 16; i++) {
            S  += (double)d_part[(g * 16 + i) * 2 + 0];
            SS += (double)d_part[(g * 16 + i) * 2 + 1];
        }
        const double n = (double)NPG;
        double mu  = S / n;
        double var = SS / n - mu * mu;
        smu[threadIdx.x]   = (float)mu;
        srstd[threadIdx.x] = (float)(1.0 / sqrt(var + 1e-5));
    }
    __syncthreads();
    const int base = slice * 1024;
#pragma unroll 4
    for (int i = 0; i < 4; i++) {
        int idx = base + i * 256 + threadIdx.x;
        int k = idx >> 7, o = idx & 127;
        float w = (o < 64) ? gw[o * 64 + k] : uw[(o - 64) * 64 + k];
        // interleaved: [k][c*2 + {0=gate,1=upd}]
        d_weff[b * 8192 + k * 128 + (o & 63) * 2 + (o >> 6)] =
            w * gnw[k] * srstd[k >> 3];
    }
    if (slice == 0 && threadIdx.x < 128) {
        int o = threadIdx.x;
        float acc = (o < 64) ? gb[o] : ub[o - 64];
#pragma unroll 8
        for (int k = 0; k < 64; k++) {
            float w = (o < 64) ? gw[o * 64 + k] : uw[(o - 64) * 64 + k];
            int g = k >> 3;
            acc += w * (gnb[k] - smu[g] * srstd[g] * gnw[k]);
        }
        d_biaseff[b * 128 + o] = acc;
    }
}

// ---------------- dummy: shifts colscan to profiled launch slot #4 -------
__global__ void k_nop() {}

// ---------------- K3: persistent fused 1x1 convs + column scan -----------
// Grid 592 = 148 SMs x 4 CTAs (one wave). Each CTA pops (b,h) rows from
// d_ctr until exhausted; weights reload only on batch change. Inner loop
// is the proven R7 body: c = t>>1, wg = t&1, 32-px chunks, per k per
// thread 1 LDS.64 + 4 broadcast LDS.128 -> 16 FFMA2.
__global__ __launch_bounds__(128, 4) void k_colscan(const float* __restrict__ x) {
    __shared__ float wsm[64 * 128];   // 32KB: [k][c*2 + {g,u}]
    __shared__ float hv[64 * 36];     // 9.2KB: [k][32 px + 4 pad]
    __shared__ int   s_row;

    const int t  = threadIdx.x;
    const int c  = t >> 1;
    const int wg = t & 1;
    const unsigned FULL = 0xffffffffu;

    int cur_b = -1;
    float bg = 0.f, bu = 0.f;

    for (;;) {
        if (t == 0) s_row = atomicAdd(&d_ctr, 1);
        __syncthreads();                        // s_row visible to all
        const int row = s_row;
        if (row >= 2048) break;
        const int b = row >> 8;
        const int h = row & 255;

        if (b != cur_b) {
            cur_b = b;
            const float4* wsrc = (const float4*)(d_weff + b * 8192);
            float4* wdst = (float4*)wsm;
#pragma unroll
            for (int i = 0; i < 16; i++) wdst[t + i * 128] = wsrc[t + i * 128];
            bg = d_biaseff[b * 128 + c];
            bu = d_biaseff[b * 128 + 64 + c];
            // wsm visibility covered by the post-staging barrier below
        }

        // loader slots: sl = t + i*128 -> channel sl>>3, float4 slot sl&7
        const float* xb = x + (size_t)b * 64 * 65536 + h * 256;
        const float* gptr[4];
        int soff[4];
#pragma unroll
        for (int i = 0; i < 4; i++) {
            int sl = t + i * 128;
            gptr[i] = xb + (size_t)(sl >> 3) * 65536 + (sl & 7) * 4;
            soff[i] = (sl >> 3) * 36 + (sl & 7) * 4;
        }
        float4 vin[4];
#pragma unroll
        for (int i = 0; i < 4; i++) vin[i] = *(const float4*)gptr[i];

        float s_prev = 0.f;

#pragma unroll 1
        for (int chk = 0; chk < 8; chk++) {
            if (chk) __syncthreads();          // prior readers of hv done
#pragma unroll
            for (int i = 0; i < 4; i++) *(float4*)&hv[soff[i]] = vin[i];
            __syncthreads();                   // chunk (and wsm on first use) visible
            if (chk < 7) {
#pragma unroll
                for (int i = 0; i < 4; i++)
                    vin[i] = *(const float4*)(gptr[i] + (chk + 1) * 32);
            }

            // ---- matvec: 16 pixels x {gate, upd} ----
            unsigned long long ag[8], au[8];
            const unsigned long long bg2 = pack2(bg, bg);
            const unsigned long long bu2 = pack2(bu, bu);
#pragma unroll
            for (int j = 0; j < 8; j++) { ag[j] = bg2; au[j] = bu2; }
            const float* hb = hv + wg * 16;
#pragma unroll
            for (int k = 0; k < 64; k++) {
                float2 wv = *(const float2*)&wsm[k * 128 + c * 2];
                unsigned long long w2g = pack2(wv.x, wv.x);
                unsigned long long w2u = pack2(wv.y, wv.y);
#pragma unroll
                for (int j = 0; j < 4; j++) {
                    ulonglong2 hp = *(const ulonglong2*)(hb + k * 36 + j * 4);
                    ag[2*j]   = fma2(w2g, hp.x, ag[2*j]);
                    au[2*j]   = fma2(w2u, hp.x, au[2*j]);
                    ag[2*j+1] = fma2(w2g, hp.y, ag[2*j+1]);
                    au[2*j+1] = fma2(w2u, hp.y, au[2*j+1]);
                }
            }
            float gv[16], uv[16];
#pragma unroll
            for (int j = 0; j < 8; j++) {
                unpack2(ag[j], gv[2*j], gv[2*j+1]);
                unpack2(au[j], uv[2*j], uv[2*j+1]);
            }
            // gv -> sigmoid(gate); uv -> (1-g)*u
#pragma unroll
            for (int j = 0; j < 16; j++) {
                gv[j] = sigmoid_tanh(gv[j]);
                uv[j] = fmaf(-gv[j], uv[j], uv[j]);
            }

            // ---- composite over own 16 px ----
            float Ac = 1.f, Bc = 0.f;
#pragma unroll
            for (int j = 0; j < 16; j++) {
                Ac = Ac * gv[j];
                Bc = fmaf(gv[j], Bc, uv[j]);
            }
            // exchange with neighbour 16-px group (lane^1)
            float Ao = __shfl_xor_sync(FULL, Ac, 1);
            float Bo = __shfl_xor_sync(FULL, Bc, 1);
            float Af = (wg == 0) ? Ac : Ao;   // first-half composite
            float Bf = (wg == 0) ? Bc : Bo;
            float As = (wg == 0) ? Ao : Ac;   // second-half composite
            float Bs = (wg == 0) ? Bo : Bc;
            float sin = (wg == 0) ? s_prev : fmaf(Af, s_prev, Bf);
            s_prev = fmaf(As, fmaf(Af, s_prev, Bf), Bs);

            // ---- sequential re-apply + writeback (4+4 STG.128) ----
            int gi = (((b * 64 + c) * 256 + h) * 256) + chk * 32 + wg * 16;
            float s = sin;
#pragma unroll
            for (int q = 0; q < 4; q++) {
                float4 sv4;
                s = fmaf(gv[4*q+0], s, uv[4*q+0]); sv4.x = s;
                s = fmaf(gv[4*q+1], s, uv[4*q+1]); sv4.y = s;
                s = fmaf(gv[4*q+2], s, uv[4*q+2]); sv4.z = s;
                s = fmaf(gv[4*q+3], s, uv[4*q+3]); sv4.w = s;
                *(float4*)(d_gate + gi + q * 4) =
                    make_float4(gv[4*q], gv[4*q+1], gv[4*q+2], gv[4*q+3]);
                *(float4*)(d_hw + gi + q * 4) = sv4;
            }
        }
        __syncthreads();   // row done: hv/s_row safe to reuse on next pop
    }
}

// ---------------- K4: row scan over H + residual add ---------------------
__global__ __launch_bounds__(128) void k_rowscan(const float* __restrict__ x,
                                                 float* __restrict__ out) {
    const int idx  = blockIdx.x * 128 + threadIdx.x;     // 0..131071
    const int base = (idx >> 8) * 65536 + (idx & 255);   // (b*64+c)*HW + w
    float s = 0.f;
#pragma unroll 1
    for (int h = 0; h < 256; h += 8) {
        const int r = base + (h << 8);
        float g[8], u[8], xv[8];
#pragma unroll
        for (int j = 0; j < 8; j++) g[j] = d_gate[r + (j << 8)];
#pragma unroll
        for (int j = 0; j < 8; j++) u[j] = d_hw[r + (j << 8)];
#pragma unroll
        for (int j = 0; j < 8; j++) xv[j] = __ldcs(&x[r + (j << 8)]);
#pragma unroll
        for (int j = 0; j < 8; j++) {
            s = fmaf(g[j], s, fmaf(-g[j], u[j], u[j]));
            __stcs(&out[r + (j << 8)], xv[j] + s);
        }
    }
}

// ---------------- launch --------------------------------------------------
extern "C" void kernel_launch(void* const* d_in, const int* in_sizes, int n_in,
                              void* d_out, int out_size) {
    const float* x      = (const float*)d_in[0];
    const float* gn_w   = (const float*)d_in[1];
    const float* gn_b   = (const float*)d_in[2];
    const float* gate_w = (const float*)d_in[3];
    const float* gate_b = (const float*)d_in[4];
    const float* upd_w  = (const float*)d_in[5];
    const float* upd_b  = (const float*)d_in[6];
    float* out = (float*)d_out;

    k_gn_stats<<<1024, 256>>>(x);
    k_weff<<<64, 256>>>(gate_w, gate_b, upd_w, upd_b, gn_w, gn_b);
    k_nop<<<1, 32>>>();                 // shifts k_colscan into profiled slot
    k_colscan<<<592, 128>>>(x);
    k_rowscan<<<1024, 128>>>(x, out);
}

// round 13
// speedup vs baseline: 1.3292x; 1.0695x over previous
#include <cuda_runtime.h>
#include <cstdint>

#define NPG 524288           // elements per (b, group)
#define NTOT 33554432        // B*C*H*W

// ---------------- device scratch (static allocation only) ----------------
static __device__ float  d_part[1024 * 2];    // per-block GN partials (sum, sumsq)
static __device__ float  d_weff[8 * 8192];    // [b][k][slot], slot = (c>>1)*4+(c&1)*2+gu
static __device__ float  d_biaseff[8 * 128];  // [b][slot]
static __device__ float  d_gate[NTOT];        // sigmoid(gate logits)
static __device__ float  d_hw[NTOT];          // column-scan result

// ---------------- f32x2 packed FMA helpers --------------------------------
__device__ __forceinline__ unsigned long long fma2(unsigned long long a,
                                                   unsigned long long b,
                                                   unsigned long long c) {
    unsigned long long d;
    asm("fma.rn.f32x2 %0, %1, %2, %3;" : "=l"(d) : "l"(a), "l"(b), "l"(c));
    return d;
}
__device__ __forceinline__ unsigned long long pack2(float lo, float hi) {
    unsigned long long d;
    asm("mov.b64 %0, {%1, %2};" : "=l"(d) : "f"(lo), "f"(hi));
    return d;
}
__device__ __forceinline__ void unpack2(unsigned long long v, float& lo, float& hi) {
    asm("mov.b64 {%0, %1}, %2;" : "=f"(lo), "=f"(hi) : "l"(v));
}
// sigmoid(z) = 0.5*tanh(0.5z) + 0.5 via MUFU.TANH
__device__ __forceinline__ float sigmoid_tanh(float z) {
    float t;
    asm("tanh.approx.f32 %0, %1;" : "=f"(t) : "f"(z * 0.5f));
    return fmaf(0.5f, t, 0.5f);
}

// ---------------- K1: GN partial stats (atomic-free) ---------------------
__global__ __launch_bounds__(256) void k_gn_stats(const float* __restrict__ x) {
    const int grp   = blockIdx.x >> 4;
    const int slice = blockIdx.x & 15;
    const float4* p = (const float4*)x + (size_t)grp * 131072 + slice * 8192;
    float s = 0.f, ss = 0.f;
#pragma unroll 4
    for (int i = threadIdx.x; i < 8192; i += 256) {
        float4 v = p[i];
        s  += (v.x + v.y) + (v.z + v.w);
        ss += (v.x * v.x + v.y * v.y) + (v.z * v.z + v.w * v.w);
    }
    for (int off = 16; off; off >>= 1) {
        s  += __shfl_down_sync(0xffffffffu, s,  off);
        ss += __shfl_down_sync(0xffffffffu, ss, off);
    }
    __shared__ float rs[8], rss[8];
    int w = threadIdx.x >> 5, l = threadIdx.x & 31;
    if (l == 0) { rs[w] = s; rss[w] = ss; }
    __syncthreads();
    if (threadIdx.x == 0) {
        float S = 0.f, SS = 0.f;
#pragma unroll
        for (int i = 0; i < 8; i++) { S += rs[i]; SS += rss[i]; }
        d_part[blockIdx.x * 2 + 0] = S;
        d_part[blockIdx.x * 2 + 1] = SS;
    }
}

// ---------------- K2: finalize stats + fold GN affine into weights -------
// Slot layout: slot(c, gu) = (c>>1)*4 + (c&1)*2 + gu so the 4 outputs a
// thread owns ({gate,upd} x {2cp, 2cp+1}) are 16B-adjacent.
__global__ __launch_bounds__(256) void k_weff(const float* __restrict__ gw,
                                              const float* __restrict__ gb,
                                              const float* __restrict__ uw,
                                              const float* __restrict__ ub,
                                              const float* __restrict__ gnw,
                                              const float* __restrict__ gnb) {
    const int b = blockIdx.x >> 3;
    const int slice = blockIdx.x & 7;
    __shared__ float smu[8], srstd[8];
    if (threadIdx.x < 8) {
        int g = b * 8 + threadIdx.x;
        double S = 0.0, SS = 0.0;
#pragma unroll
        for (int i = 0; i < 16; i++) {
            S  += (double)d_part[(g * 16 + i) * 2 + 0];
            SS += (double)d_part[(g * 16 + i) * 2 + 1];
        }
        const double n = (double)NPG;
        double mu  = S / n;
        double var = SS / n - mu * mu;
        smu[threadIdx.x]   = (float)mu;
        srstd[threadIdx.x] = (float)(1.0 / sqrt(var + 1e-5));
    }
    __syncthreads();
    const int base = slice * 1024;
#pragma unroll 4
    for (int i = 0; i < 4; i++) {
        int idx = base + i * 256 + threadIdx.x;
        int k = idx >> 7, o = idx & 127;
        int c = o & 63, gu = o >> 6;
        float w = gu ? uw[c * 64 + k] : gw[c * 64 + k];
        int slot = (c >> 1) * 4 + (c & 1) * 2 + gu;
        d_weff[b * 8192 + k * 128 + slot] = w * gnw[k] * srstd[k >> 3];
    }
    if (slice == 0 && threadIdx.x < 128) {
        int o = threadIdx.x;
        int c = o & 63, gu = o >> 6;
        float acc = gu ? ub[c] : gb[c];
#pragma unroll 8
        for (int k = 0; k < 64; k++) {
            float w = gu ? uw[c * 64 + k] : gw[c * 64 + k];
            int g = k >> 3;
            acc += w * (gnb[k] - smu[g] * srstd[g] * gnw[k]);
        }
        d_biaseff[b * 128 + (c >> 1) * 4 + (c & 1) * 2 + gu] = acc;
    }
}

// ---------------- dummy: keeps colscan in profiled launch slot #4 --------
__global__ void k_nop() {}

// ---------------- K3: fused 1x1 convs + column scan over W ---------------
// Grid 2048 = 8 b x 256 h, 128 threads, 4 CTAs/SM. Thread tile: 2 channels
// (cp = t>>2) x 8 px (q = t&3). Per k per thread: 1 LDS.128 (4 weights) +
// 2 LDS.128 (8 px) -> 16 FFMA2. 3 loads/16 fma2 vs R7's 5 -> crossbar
// demand cut 40%; fma becomes the binding pipe.
__global__ __launch_bounds__(128, 4) void k_colscan(const float* __restrict__ x) {
    __shared__ float wsm[64 * 128];   // 32KB: [k][slot]
    __shared__ float hv[64 * 36];     // 9.2KB: [k][32 px + 4 pad]

    const int t  = threadIdx.x;
    const int b  = blockIdx.x >> 8;
    const int h  = blockIdx.x & 255;
    const int cp = t >> 2;            // channel pair: owns channels 2cp, 2cp+1
    const int q  = t & 3;             // 8-px group within 32-px chunk
    const unsigned FULL = 0xffffffffu;

    {
        const float4* wsrc = (const float4*)(d_weff + b * 8192);
        float4* wdst = (float4*)wsm;
#pragma unroll
        for (int i = 0; i < 16; i++) wdst[t + i * 128] = wsrc[t + i * 128];
    }
    const float4 bias = *(const float4*)&d_biaseff[b * 128 + cp * 4];

    // loader slots: sl = t + i*128 -> channel sl>>3, float4 slot sl&7
    const float* xb = x + (size_t)b * 64 * 65536 + h * 256;
    const float* gptr[4];
    int soff[4];
#pragma unroll
    for (int i = 0; i < 4; i++) {
        int sl = t + i * 128;
        gptr[i] = xb + (size_t)(sl >> 3) * 65536 + (sl & 7) * 4;
        soff[i] = (sl >> 3) * 36 + (sl & 7) * 4;
    }
    float4 vin[4];
#pragma unroll
    for (int i = 0; i < 4; i++) vin[i] = *(const float4*)gptr[i];

    float s_prev0 = 0.f, s_prev1 = 0.f;

#pragma unroll 1
    for (int chk = 0; chk < 8; chk++) {
        if (chk) __syncthreads();          // prior readers of hv done
#pragma unroll
        for (int i = 0; i < 4; i++) *(float4*)&hv[soff[i]] = vin[i];
        __syncthreads();                   // chunk (and wsm on chk=0) visible
        if (chk < 7) {
#pragma unroll
            for (int i = 0; i < 4; i++)
                vin[i] = *(const float4*)(gptr[i] + (chk + 1) * 32);
        }

        // ---- matvec: 4 outputs x 8 px ----
        unsigned long long acc[4][4];
        {
            unsigned long long b0 = pack2(bias.x, bias.x);
            unsigned long long b1 = pack2(bias.y, bias.y);
            unsigned long long b2 = pack2(bias.z, bias.z);
            unsigned long long b3 = pack2(bias.w, bias.w);
#pragma unroll
            for (int p = 0; p < 4; p++) {
                acc[0][p] = b0; acc[1][p] = b1; acc[2][p] = b2; acc[3][p] = b3;
            }
        }
        const float* hb = hv + q * 8;
#pragma unroll
        for (int k = 0; k < 64; k++) {
            float4 w = *(const float4*)&wsm[k * 128 + cp * 4];
            ulonglong2 pA = *(const ulonglong2*)(hb + k * 36);
            ulonglong2 pB = *(const ulonglong2*)(hb + k * 36 + 4);
            unsigned long long w0 = pack2(w.x, w.x);
            unsigned long long w1 = pack2(w.y, w.y);
            unsigned long long w2 = pack2(w.z, w.z);
            unsigned long long w3 = pack2(w.w, w.w);
            acc[0][0] = fma2(w0, pA.x, acc[0][0]);
            acc[0][1] = fma2(w0, pA.y, acc[0][1]);
            acc[0][2] = fma2(w0, pB.x, acc[0][2]);
            acc[0][3] = fma2(w0, pB.y, acc[0][3]);
            acc[1][0] = fma2(w1, pA.x, acc[1][0]);
            acc[1][1] = fma2(w1, pA.y, acc[1][1]);
            acc[1][2] = fma2(w1, pB.x, acc[1][2]);
            acc[1][3] = fma2(w1, pB.y, acc[1][3]);
            acc[2][0] = fma2(w2, pA.x, acc[2][0]);
            acc[2][1] = fma2(w2, pA.y, acc[2][1]);
            acc[2][2] = fma2(w2, pB.x, acc[2][2]);
            acc[2][3] = fma2(w2, pB.y, acc[2][3]);
            acc[3][0] = fma2(w3, pA.x, acc[3][0]);
            acc[3][1] = fma2(w3, pA.y, acc[3][1]);
            acc[3][2] = fma2(w3, pB.x, acc[3][2]);
            acc[3][3] = fma2(w3, pB.y, acc[3][3]);
        }
        // unpack: gv/uv per channel, 8 px each
        float gv0[8], uv0[8], gv1[8], uv1[8];
#pragma unroll
        for (int p = 0; p < 4; p++) {
            unpack2(acc[0][p], gv0[2*p], gv0[2*p+1]);
            unpack2(acc[1][p], uv0[2*p], uv0[2*p+1]);
            unpack2(acc[2][p], gv1[2*p], gv1[2*p+1]);
            unpack2(acc[3][p], uv1[2*p], uv1[2*p+1]);
        }
#pragma unroll
        for (int j = 0; j < 8; j++) {
            gv0[j] = sigmoid_tanh(gv0[j]);
            uv0[j] = fmaf(-gv0[j], uv0[j], uv0[j]);   // (1-g)*u
            gv1[j] = sigmoid_tanh(gv1[j]);
            uv1[j] = fmaf(-gv1[j], uv1[j], uv1[j]);
        }

        // ---- scan channel 0: composite + width-4 Hillis-Steele ----
        {
            float Ac = 1.f, Bc = 0.f;
#pragma unroll
            for (int j = 0; j < 8; j++) {
                Ac = Ac * gv0[j];
                Bc = fmaf(gv0[j], Bc, uv0[j]);
            }
            float Ai = Ac, Bi = Bc;
            float Au = __shfl_up_sync(FULL, Ai, 1, 4);
            float Bu = __shfl_up_sync(FULL, Bi, 1, 4);
            if (q >= 1) { Bi = fmaf(Ai, Bu, Bi); Ai *= Au; }
            Au = __shfl_up_sync(FULL, Ai, 2, 4);
            Bu = __shfl_up_sync(FULL, Bi, 2, 4);
            if (q >= 2) { Bi = fmaf(Ai, Bu, Bi); Ai *= Au; }
            float Ax = __shfl_up_sync(FULL, Ai, 1, 4);
            float Bx = __shfl_up_sync(FULL, Bi, 1, 4);
            float sin0 = (q == 0) ? s_prev0 : fmaf(Ax, s_prev0, Bx);
            float A3 = __shfl_sync(FULL, Ai, 3, 4);
            float B3 = __shfl_sync(FULL, Bi, 3, 4);
            s_prev0 = fmaf(A3, s_prev0, B3);

            int gi = (((b * 64 + 2 * cp) * 256 + h) * 256) + chk * 32 + q * 8;
            float s = sin0;
            float4 sv0, sv1;
            s = fmaf(gv0[0], s, uv0[0]); sv0.x = s;
            s = fmaf(gv0[1], s, uv0[1]); sv0.y = s;
            s = fmaf(gv0[2], s, uv0[2]); sv0.z = s;
            s = fmaf(gv0[3], s, uv0[3]); sv0.w = s;
            s = fmaf(gv0[4], s, uv0[4]); sv1.x = s;
            s = fmaf(gv0[5], s, uv0[5]); sv1.y = s;
            s = fmaf(gv0[6], s, uv0[6]); sv1.z = s;
            s = fmaf(gv0[7], s, uv0[7]); sv1.w = s;
            *(float4*)(d_gate + gi)     = make_float4(gv0[0], gv0[1], gv0[2], gv0[3]);
            *(float4*)(d_gate + gi + 4) = make_float4(gv0[4], gv0[5], gv0[6], gv0[7]);
            *(float4*)(d_hw + gi)       = sv0;
            *(float4*)(d_hw + gi + 4)   = sv1;
        }
        // ---- scan channel 1 ----
        {
            float Ac = 1.f, Bc = 0.f;
#pragma unroll
            for (int j = 0; j < 8; j++) {
                Ac = Ac * gv1[j];
                Bc = fmaf(gv1[j], Bc, uv1[j]);
            }
            float Ai = Ac, Bi = Bc;
            float Au = __shfl_up_sync(FULL, Ai, 1, 4);
            float Bu = __shfl_up_sync(FULL, Bi, 1, 4);
            if (q >= 1) { Bi = fmaf(Ai, Bu, Bi); Ai *= Au; }
            Au = __shfl_up_sync(FULL, Ai, 2, 4);
            Bu = __shfl_up_sync(FULL, Bi, 2, 4);
            if (q >= 2) { Bi = fmaf(Ai, Bu, Bi); Ai *= Au; }
            float Ax = __shfl_up_sync(FULL, Ai, 1, 4);
            float Bx = __shfl_up_sync(FULL, Bi, 1, 4);
            float sin1 = (q == 0) ? s_prev1 : fmaf(Ax, s_prev1, Bx);
            float A3 = __shfl_sync(FULL, Ai, 3, 4);
            float B3 = __shfl_sync(FULL, Bi, 3, 4);
            s_prev1 = fmaf(A3, s_prev1, B3);

            int gi = (((b * 64 + 2 * cp + 1) * 256 + h) * 256) + chk * 32 + q * 8;
            float s = sin1;
            float4 sv0, sv1;
            s = fmaf(gv1[0], s, uv1[0]); sv0.x = s;
            s = fmaf(gv1[1], s, uv1[1]); sv0.y = s;
            s = fmaf(gv1[2], s, uv1[2]); sv0.z = s;
            s = fmaf(gv1[3], s, uv1[3]); sv0.w = s;
            s = fmaf(gv1[4], s, uv1[4]); sv1.x = s;
            s = fmaf(gv1[5], s, uv1[5]); sv1.y = s;
            s = fmaf(gv1[6], s, uv1[6]); sv1.z = s;
            s = fmaf(gv1[7], s, uv1[7]); sv1.w = s;
            *(float4*)(d_gate + gi)     = make_float4(gv1[0], gv1[1], gv1[2], gv1[3]);
            *(float4*)(d_gate + gi + 4) = make_float4(gv1[4], gv1[5], gv1[6], gv1[7]);
            *(float4*)(d_hw + gi)       = sv0;
            *(float4*)(d_hw + gi + 4)   = sv1;
        }
    }
}

// ---------------- K4: row scan over H + residual add ---------------------
__global__ __launch_bounds__(128) void k_rowscan(const float* __restrict__ x,
                                                 float* __restrict__ out) {
    const int idx  = blockIdx.x * 128 + threadIdx.x;     // 0..131071
    const int base = (idx >> 8) * 65536 + (idx & 255);   // (b*64+c)*HW + w
    float s = 0.f;
#pragma unroll 1
    for (int h = 0; h < 256; h += 8) {
        const int r = base + (h << 8);
        float g[8], u[8], xv[8];
#pragma unroll
        for (int j = 0; j < 8; j++) g[j] = d_gate[r + (j << 8)];
#pragma unroll
        for (int j = 0; j < 8; j++) u[j] = d_hw[r + (j << 8)];
#pragma unroll
        for (int j = 0; j < 8; j++) xv[j] = __ldcs(&x[r + (j << 8)]);
#pragma unroll
        for (int j = 0; j < 8; j++) {
            s = fmaf(g[j], s, fmaf(-g[j], u[j], u[j]));
            __stcs(&out[r + (j << 8)], xv[j] + s);
        }
    }
}

// ---------------- launch --------------------------------------------------
extern "C" void kernel_launch(void* const* d_in, const int* in_sizes, int n_in,
                              void* d_out, int out_size) {
    const float* x      = (const float*)d_in[0];
    const float* gn_w   = (const float*)d_in[1];
    const float* gn_b   = (const float*)d_in[2];
    const float* gate_w = (const float*)d_in[3];
    const float* gate_b = (const float*)d_in[4];
    const float* upd_w  = (const float*)d_in[5];
    const float* upd_b  = (const float*)d_in[6];
    float* out = (float*)d_out;

    k_gn_stats<<<1024, 256>>>(x);
    k_weff<<<64, 256>>>(gate_w, gate_b, upd_w, upd_b, gn_w, gn_b);
    k_nop<<<1, 32>>>();                 // keeps k_colscan in profiled slot
    k_colscan<<<2048, 128>>>(x);
    k_rowscan<<<1024, 128>>>(x, out);
}

// round 14
// speedup vs baseline: 1.3332x; 1.0030x over previous
#include <cuda_runtime.h>
#include <cstdint>

#define NPG 524288           // elements per (b, group)
#define NTOT 33554432        // B*C*H*W

// ---------------- device scratch (static allocation only) ----------------
static __device__ float  d_part[1024 * 2];    // per-block GN partials (sum, sumsq)
static __device__ float  d_weff[8 * 8192];    // [b][k][slot], slot=(c>>2)*8+(c&3)*2+gu
static __device__ float  d_biaseff[8 * 128];  // [b][slot]
static __device__ float  d_gate[NTOT];        // sigmoid(gate logits)
static __device__ float  d_hw[NTOT];          // column-scan result

// ---------------- f32x2 packed FMA helpers --------------------------------
__device__ __forceinline__ unsigned long long fma2(unsigned long long a,
                                                   unsigned long long b,
                                                   unsigned long long c) {
    unsigned long long d;
    asm("fma.rn.f32x2 %0, %1, %2, %3;" : "=l"(d) : "l"(a), "l"(b), "l"(c));
    return d;
}
__device__ __forceinline__ unsigned long long pack2(float lo, float hi) {
    unsigned long long d;
    asm("mov.b64 %0, {%1, %2};" : "=l"(d) : "f"(lo), "f"(hi));
    return d;
}
__device__ __forceinline__ void unpack2(unsigned long long v, float& lo, float& hi) {
    asm("mov.b64 {%0, %1}, %2;" : "=f"(lo), "=f"(hi) : "l"(v));
}
// sigmoid(z) = 0.5*tanh(0.5z) + 0.5 via MUFU.TANH
__device__ __forceinline__ float sigmoid_tanh(float z) {
    float t;
    asm("tanh.approx.f32 %0, %1;" : "=f"(t) : "f"(z * 0.5f));
    return fmaf(0.5f, t, 0.5f);
}

// ---------------- K1: GN partial stats (atomic-free) ---------------------
__global__ __launch_bounds__(256) void k_gn_stats(const float* __restrict__ x) {
    const int grp   = blockIdx.x >> 4;
    const int slice = blockIdx.x & 15;
    const float4* p = (const float4*)x + (size_t)grp * 131072 + slice * 8192;
    float s = 0.f, ss = 0.f;
#pragma unroll 4
    for (int i = threadIdx.x; i < 8192; i += 256) {
        float4 v = p[i];
        s  += (v.x + v.y) + (v.z + v.w);
        ss += (v.x * v.x + v.y * v.y) + (v.z * v.z + v.w * v.w);
    }
    for (int off = 16; off; off >>= 1) {
        s  += __shfl_down_sync(0xffffffffu, s,  off);
        ss += __shfl_down_sync(0xffffffffu, ss, off);
    }
    __shared__ float rs[8], rss[8];
    int w = threadIdx.x >> 5, l = threadIdx.x & 31;
    if (l == 0) { rs[w] = s; rss[w] = ss; }
    __syncthreads();
    if (threadIdx.x == 0) {
        float S = 0.f, SS = 0.f;
#pragma unroll
        for (int i = 0; i < 8; i++) { S += rs[i]; SS += rss[i]; }
        d_part[blockIdx.x * 2 + 0] = S;
        d_part[blockIdx.x * 2 + 1] = SS;
    }
}

// ---------------- K2: finalize stats + fold GN affine into weights -------
// Slot layout: slot(c, gu) = (c>>2)*8 + (c&3)*2 + gu so the 8 outputs a
// thread owns ({gate,upd} x channels 4q..4q+3) are 32B-adjacent.
__global__ __launch_bounds__(256) void k_weff(const float* __restrict__ gw,
                                              const float* __restrict__ gb,
                                              const float* __restrict__ uw,
                                              const float* __restrict__ ub,
                                              const float* __restrict__ gnw,
                                              const float* __restrict__ gnb) {
    const int b = blockIdx.x >> 3;
    const int slice = blockIdx.x & 7;
    __shared__ float smu[8], srstd[8];
    if (threadIdx.x < 8) {
        int g = b * 8 + threadIdx.x;
        double S = 0.0, SS = 0.0;
#pragma unroll
        for (int i = 0; i < 16; i++) {
            S  += (double)d_part[(g * 16 + i) * 2 + 0];
            SS += (double)d_part[(g * 16 + i) * 2 + 1];
        }
        const double n = (double)NPG;
        double mu  = S / n;
        double var = SS / n - mu * mu;
        smu[threadIdx.x]   = (float)mu;
        srstd[threadIdx.x] = (float)(1.0 / sqrt(var + 1e-5));
    }
    __syncthreads();
    const int base = slice * 1024;
#pragma unroll 4
    for (int i = 0; i < 4; i++) {
        int idx = base + i * 256 + threadIdx.x;
        int k = idx >> 7, o = idx & 127;
        int c = o & 63, gu = o >> 6;
        float w = gu ? uw[c * 64 + k] : gw[c * 64 + k];
        int slot = (c >> 2) * 8 + (c & 3) * 2 + gu;
        d_weff[b * 8192 + k * 128 + slot] = w * gnw[k] * srstd[k >> 3];
    }
    if (slice == 0 && threadIdx.x < 128) {
        int o = threadIdx.x;
        int c = o & 63, gu = o >> 6;
        float acc = gu ? ub[c] : gb[c];
#pragma unroll 8
        for (int k = 0; k < 64; k++) {
            float w = gu ? uw[c * 64 + k] : gw[c * 64 + k];
            int g = k >> 3;
            acc += w * (gnb[k] - smu[g] * srstd[g] * gnw[k]);
        }
        d_biaseff[b * 128 + (c >> 2) * 8 + (c & 3) * 2 + gu] = acc;
    }
}

// ---------------- dummy: keeps colscan in profiled launch slot #4 --------
__global__ void k_nop() {}

// ---------------- K3: fused 1x1 convs + column scan over W ---------------
// Grid 2048 = 8 b x 256 h, 128 threads, 3 CTAs/SM (48KB smem, <=170 regs).
// Thread tile: 4 channels (og = t>>3, channels 4og..4og+3) x 8 px
// (q = t&7); chunk = 64 px, 4 chunks/row. Per k per thread: 2 LDS.128
// (8 weights) + 2 LDS.128 (8 px) -> 32 FFMA2. Ratio 4/32 vs R13's 3/16.
__global__ __launch_bounds__(128, 3) void k_colscan(const float* __restrict__ x) {
    __shared__ float wsm[64 * 128];   // 32KB: [k][slot]
    __shared__ float hv[64 * 64];     // 16KB: [k][64 px]  (total = 48KB exactly)

    const int t  = threadIdx.x;
    const int b  = blockIdx.x >> 8;
    const int h  = blockIdx.x & 255;
    const int og = t >> 3;            // 0..15: owns channels 4og..4og+3
    const int q  = t & 7;             // 8-px group within 64-px chunk
    const unsigned FULL = 0xffffffffu;

    {
        const float4* wsrc = (const float4*)(d_weff + b * 8192);
        float4* wdst = (float4*)wsm;
#pragma unroll
        for (int i = 0; i < 16; i++) wdst[t + i * 128] = wsrc[t + i * 128];
    }
    const float4 bias0 = *(const float4*)&d_biaseff[b * 128 + og * 8];
    const float4 bias1 = *(const float4*)&d_biaseff[b * 128 + og * 8 + 4];

    // loaders: 8 float4/thread/chunk. sl = t + i*128 -> ch = sl>>4, f = sl&15
    const float* xb = x + (size_t)b * 64 * 65536 + h * 256;
    const float* gptr[8];
    int soff[8];
#pragma unroll
    for (int i = 0; i < 8; i++) {
        int sl = t + i * 128;
        gptr[i] = xb + (size_t)(sl >> 4) * 65536 + (sl & 15) * 4;
        soff[i] = (sl >> 4) * 64 + (sl & 15) * 4;
    }
    float4 vin[8];
#pragma unroll
    for (int i = 0; i < 8; i++) vin[i] = *(const float4*)gptr[i];

    float sp0 = 0.f, sp1 = 0.f, sp2 = 0.f, sp3 = 0.f;

#pragma unroll 1
    for (int chk = 0; chk < 4; chk++) {
        if (chk) __syncthreads();          // prior readers of hv done
#pragma unroll
        for (int i = 0; i < 8; i++) *(float4*)&hv[soff[i]] = vin[i];
        __syncthreads();                   // chunk (and wsm on chk=0) visible
        if (chk < 3) {
#pragma unroll
            for (int i = 0; i < 8; i++)
                vin[i] = *(const float4*)(gptr[i] + (chk + 1) * 64);
        }

        // ---- matvec: 8 outputs x 8 px ----
        unsigned long long acc[8][4];
        {
            float bb[8] = {bias0.x, bias0.y, bias0.z, bias0.w,
                           bias1.x, bias1.y, bias1.z, bias1.w};
#pragma unroll
            for (int j = 0; j < 8; j++) {
                unsigned long long bj = pack2(bb[j], bb[j]);
                acc[j][0] = bj; acc[j][1] = bj; acc[j][2] = bj; acc[j][3] = bj;
            }
        }
        const float* hb = hv + q * 8;
#pragma unroll 8
        for (int k = 0; k < 64; k++) {
            float4 w0 = *(const float4*)&wsm[k * 128 + og * 8];
            float4 w1 = *(const float4*)&wsm[k * 128 + og * 8 + 4];
            ulonglong2 pA = *(const ulonglong2*)(hb + k * 64);
            ulonglong2 pB = *(const ulonglong2*)(hb + k * 64 + 4);
            float wv[8] = {w0.x, w0.y, w0.z, w0.w, w1.x, w1.y, w1.z, w1.w};
#pragma unroll
            for (int j = 0; j < 8; j++) {
                unsigned long long w2 = pack2(wv[j], wv[j]);
                acc[j][0] = fma2(w2, pA.x, acc[j][0]);
                acc[j][1] = fma2(w2, pA.y, acc[j][1]);
                acc[j][2] = fma2(w2, pB.x, acc[j][2]);
                acc[j][3] = fma2(w2, pB.y, acc[j][3]);
            }
        }

        // ---- per-channel scan (4 channels, static unroll) ----
#pragma unroll
        for (int cl = 0; cl < 4; cl++) {
            float gv[8], uv[8];
#pragma unroll
            for (int p = 0; p < 4; p++) {
                unpack2(acc[2 * cl][p],     gv[2*p], gv[2*p+1]);
                unpack2(acc[2 * cl + 1][p], uv[2*p], uv[2*p+1]);
            }
#pragma unroll
            for (int j = 0; j < 8; j++) {
                gv[j] = sigmoid_tanh(gv[j]);
                uv[j] = fmaf(-gv[j], uv[j], uv[j]);   // (1-g)*u
            }
            // composite over own 8 px
            float Ac = 1.f, Bc = 0.f;
#pragma unroll
            for (int j = 0; j < 8; j++) {
                Ac = Ac * gv[j];
                Bc = fmaf(gv[j], Bc, uv[j]);
            }
            // width-8 inclusive Hillis-Steele over q lanes
            float Ai = Ac, Bi = Bc;
            float Au = __shfl_up_sync(FULL, Ai, 1, 8);
            float Bu = __shfl_up_sync(FULL, Bi, 1, 8);
            if (q >= 1) { Bi = fmaf(Ai, Bu, Bi); Ai *= Au; }
            Au = __shfl_up_sync(FULL, Ai, 2, 8);
            Bu = __shfl_up_sync(FULL, Bi, 2, 8);
            if (q >= 2) { Bi = fmaf(Ai, Bu, Bi); Ai *= Au; }
            Au = __shfl_up_sync(FULL, Ai, 4, 8);
            Bu = __shfl_up_sync(FULL, Bi, 4, 8);
            if (q >= 4) { Bi = fmaf(Ai, Bu, Bi); Ai *= Au; }

            float sp = (cl == 0) ? sp0 : (cl == 1) ? sp1 : (cl == 2) ? sp2 : sp3;
            float Ax = __shfl_up_sync(FULL, Ai, 1, 8);
            float Bx = __shfl_up_sync(FULL, Bi, 1, 8);
            float sin = (q == 0) ? sp : fmaf(Ax, sp, Bx);
            float A7 = __shfl_sync(FULL, Ai, 7, 8);
            float B7 = __shfl_sync(FULL, Bi, 7, 8);
            sp = fmaf(A7, sp, B7);
            if (cl == 0) sp0 = sp; else if (cl == 1) sp1 = sp;
            else if (cl == 2) sp2 = sp; else sp3 = sp;

            // sequential re-apply + writeback (2+2 STG.128)
            int gi = (((b * 64 + 4 * og + cl) * 256 + h) * 256) + chk * 64 + q * 8;
            float s = sin;
            float4 sv0, sv1;
            s = fmaf(gv[0], s, uv[0]); sv0.x = s;
            s = fmaf(gv[1], s, uv[1]); sv0.y = s;
            s = fmaf(gv[2], s, uv[2]); sv0.z = s;
            s = fmaf(gv[3], s, uv[3]); sv0.w = s;
            s = fmaf(gv[4], s, uv[4]); sv1.x = s;
            s = fmaf(gv[5], s, uv[5]); sv1.y = s;
            s = fmaf(gv[6], s, uv[6]); sv1.z = s;
            s = fmaf(gv[7], s, uv[7]); sv1.w = s;
            *(float4*)(d_gate + gi)     = make_float4(gv[0], gv[1], gv[2], gv[3]);
            *(float4*)(d_gate + gi + 4) = make_float4(gv[4], gv[5], gv[6], gv[7]);
            *(float4*)(d_hw + gi)       = sv0;
            *(float4*)(d_hw + gi + 4)   = sv1;
        }
    }
}

// ---------------- K4: row scan over H + residual add ---------------------
__global__ __launch_bounds__(128) void k_rowscan(const float* __restrict__ x,
                                                 float* __restrict__ out) {
    const int idx  = blockIdx.x * 128 + threadIdx.x;     // 0..131071
    const int base = (idx >> 8) * 65536 + (idx & 255);   // (b*64+c)*HW + w
    float s = 0.f;
#pragma unroll 1
    for (int h = 0; h < 256; h += 8) {
        const int r = base + (h << 8);
        float g[8], u[8], xv[8];
#pragma unroll
        for (int j = 0; j < 8; j++) g[j] = d_gate[r + (j << 8)];
#pragma unroll
        for (int j = 0; j < 8; j++) u[j] = d_hw[r + (j << 8)];
#pragma unroll
        for (int j = 0; j < 8; j++) xv[j] = __ldcs(&x[r + (j << 8)]);
#pragma unroll
        for (int j = 0; j < 8; j++) {
            s = fmaf(g[j], s, fmaf(-g[j], u[j], u[j]));
            __stcs(&out[r + (j << 8)], xv[j] + s);
        }
    }
}

// ---------------- launch --------------------------------------------------
extern "C" void kernel_launch(void* const* d_in, const int* in_sizes, int n_in,
                              void* d_out, int out_size) {
    const float* x      = (const float*)d_in[0];
    const float* gn_w   = (const float*)d_in[1];
    const float* gn_b   = (const float*)d_in[2];
    const float* gate_w = (const float*)d_in[3];
    const float* gate_b = (const float*)d_in[4];
    const float* upd_w  = (const float*)d_in[5];
    const float* upd_b  = (const float*)d_in[6];
    float* out = (float*)d_out;

    k_gn_stats<<<1024, 256>>>(x);
    k_weff<<<64, 256>>>(gate_w, gate_b, upd_w, upd_b, gn_w, gn_b);
    k_nop<<<1, 32>>>();                 // keeps k_colscan in profiled slot
    k_colscan<<<2048, 128>>>(x);
    k_rowscan<<<1024, 128>>>(x, out);
}